// round 6
// baseline (speedup 1.0000x reference)
#include <cuda_runtime.h>
#include <cstdint>
#include <math.h>

#define BB 8
#define TT 512
#define CC 512
#define HH 8
#define DH 64
#define CF 2048
#define MTOK (BB*TT)      // 4096
#define VV 512
#define NSTEPS 4
#define ATT_SCALE 0.125f  // 1/sqrt(64)
#define C3 (3*CC)         // 1536

// ---------------- scratch (device globals: no allocations allowed) ----------
__device__ float g_x  [MTOK*CC];
__device__ float g_xn [MTOK*CC];
__device__ float g_qkv[MTOK*C3];
__device__ float g_y  [MTOK*CC];
__device__ float g_h  [MTOK*CF];
__device__ float g_att[(size_t)BB*HH*TT*TT];
// pre-rounded (tf32) weights
__device__ float g_wqkv[2*CC*C3];
__device__ float g_bqkv[2*C3];
__device__ float g_wp  [2*CC*CC];
__device__ float g_w1  [2*CC*CF];
__device__ float g_w2  [2*CF*CC];
__device__ float g_wh  [CC*VV];

// ======================= helpers ==============================
__device__ __forceinline__ uint32_t smem_u32(const void* p) {
    uint32_t a;
    asm("{ .reg .u64 t; cvta.to.shared.u64 t, %1; cvt.u32.u64 %0, t; }"
        : "=r"(a) : "l"(p));
    return a;
}
__device__ __forceinline__ void cp_async16(uint32_t dst, const void* src) {
    asm volatile("cp.async.cg.shared.global [%0], [%1], 16;" :: "r"(dst), "l"(src));
}
__device__ __forceinline__ void cp_commit() {
    asm volatile("cp.async.commit_group;" ::: "memory");
}
template <int N>
__device__ __forceinline__ void cp_wait() {
    asm volatile("cp.async.wait_group %0;" :: "n"(N) : "memory");
}
__device__ __forceinline__ uint32_t f2tf32(float x) {
    uint32_t r;
    asm("cvt.rna.tf32.f32 %0, %1;" : "=r"(r) : "f"(x));
    return r;
}
__device__ __forceinline__ float rndf(float x) { return __uint_as_float(f2tf32(x)); }
// D += A @ B  (m16n8k8, tf32 in, fp32 accumulate)
__device__ __forceinline__ void mma8(float* c, const uint32_t* a, const uint32_t* b) {
    asm volatile(
        "mma.sync.aligned.m16n8k8.row.col.f32.tf32.tf32.f32 "
        "{%0,%1,%2,%3}, {%4,%5,%6,%7}, {%8,%9}, {%0,%1,%2,%3};"
        : "+f"(c[0]), "+f"(c[1]), "+f"(c[2]), "+f"(c[3])
        : "r"(a[0]), "r"(a[1]), "r"(a[2]), "r"(a[3]), "r"(b[0]), "r"(b[1]));
}

// ---------------- weight preprocessing (per launch, ~40us total) -----------
__global__ void prep_wqkv_k(const float* __restrict__ Wq, const float* __restrict__ Wk,
                            const float* __restrict__ Wv) {
    int i = blockIdx.x * 256 + threadIdx.x;          // over 2*CC*CC
    if (i >= 2 * CC * CC) return;
    int l = i / (CC * CC), rem = i % (CC * CC);
    int k = rem / CC, n = rem % CC;
    size_t d = ((size_t)l * CC + k) * C3;
    g_wqkv[d + n]          = rndf(Wq[i]);
    g_wqkv[d + CC + n]     = rndf(Wk[i]);
    g_wqkv[d + 2 * CC + n] = rndf(Wv[i]);
}
__global__ void prep_bqkv_k(const float* __restrict__ bq, const float* __restrict__ bk,
                            const float* __restrict__ bv) {
    int i = blockIdx.x * 256 + threadIdx.x;          // over 2*CC
    if (i >= 2 * CC) return;
    int l = i / CC, n = i % CC;
    g_bqkv[l * C3 + n]          = bq[i];
    g_bqkv[l * C3 + CC + n]     = bk[i];
    g_bqkv[l * C3 + 2 * CC + n] = bv[i];
}
__global__ void prep_round_k(const float* __restrict__ src, float* __restrict__ dst, int n) {
    int i = blockIdx.x * 256 + threadIdx.x;
    if (i < n) dst[i] = rndf(src[i]);
}

// ================== dense GEMM: out = epi(A@W + bias + res) ================
// A[M,K] row-major pre-rounded tf32; W[K,N] row-major pre-rounded tf32.
// CTA tile 128x128, 8 warps (2x4), warp tile 64x32, K-chunk 32, double buffer.
#define AS_STR 36
#define BS_STR 136
#define GEMM_SMEM (2*128*AS_STR*4 + 2*32*BS_STR*4)   // 71680 B

template <bool GELU, bool ROUND>
__global__ void __launch_bounds__(256, 2)
mma_gemm_k(const float* __restrict__ A, const float* __restrict__ W,
           const float* __restrict__ bias, const float* __restrict__ res,
           float* __restrict__ out, int M, int N, int K) {
    extern __shared__ char dsm[];
    float* As = (float*)dsm;                       // [2][128][AS_STR]
    float* Bs = As + 2 * 128 * AS_STR;             // [2][32][BS_STR]

    int tid = threadIdx.x;
    int wid = tid >> 5, lane = tid & 31;
    int g = lane >> 2, t = lane & 3;
    int mw = wid >> 2, nw = wid & 3;               // warp grid 2x4
    int m0 = blockIdx.y * 128, n0 = blockIdx.x * 128;

    auto loadA = [&](int chunk, int buf) {
        const float* src = A + (size_t)m0 * K + chunk * 32;
        float* dst = As + buf * 128 * AS_STR;
        #pragma unroll
        for (int i = 0; i < 4; i++) {
            int c = tid + i * 256;
            int m = c >> 3, s = c & 7;
            cp_async16(smem_u32(dst + m * AS_STR + s * 4),
                       src + (size_t)m * K + s * 4);
        }
    };
    auto loadB = [&](int chunk, int buf) {
        const float* src = W + (size_t)(chunk * 32) * N + n0;
        float* dst = Bs + buf * 32 * BS_STR;
        #pragma unroll
        for (int i = 0; i < 4; i++) {
            int c = tid + i * 256;
            int k = c >> 5, s = c & 31;
            cp_async16(smem_u32(dst + k * BS_STR + s * 4),
                       src + (size_t)k * N + s * 4);
        }
    };

    float acc[4][4][4];
    #pragma unroll
    for (int mi = 0; mi < 4; mi++)
        #pragma unroll
        for (int ni = 0; ni < 4; ni++)
            #pragma unroll
            for (int q = 0; q < 4; q++) acc[mi][ni][q] = 0.0f;

    const int nch = K >> 5;
    loadA(0, 0); loadB(0, 0); cp_commit();

    for (int i = 0; i < nch; i++) {
        int buf = i & 1;
        if (i + 1 < nch) {
            loadA(i + 1, buf ^ 1); loadB(i + 1, buf ^ 1); cp_commit();
            cp_wait<1>();
        } else {
            cp_wait<0>();
        }
        __syncthreads();
        const float* Ab = As + buf * 128 * AS_STR;
        const float* Bb = Bs + buf * 32 * BS_STR;
        #pragma unroll
        for (int ks = 0; ks < 4; ks++) {
            int k0 = ks * 8;
            uint32_t af[4][4], bf[4][2];
            #pragma unroll
            for (int mi = 0; mi < 4; mi++) {
                int row = mw * 64 + mi * 16;
                af[mi][0] = __float_as_uint(Ab[(row + g)     * AS_STR + k0 + t]);
                af[mi][1] = __float_as_uint(Ab[(row + 8 + g) * AS_STR + k0 + t]);
                af[mi][2] = __float_as_uint(Ab[(row + g)     * AS_STR + k0 + t + 4]);
                af[mi][3] = __float_as_uint(Ab[(row + 8 + g) * AS_STR + k0 + t + 4]);
            }
            #pragma unroll
            for (int ni = 0; ni < 4; ni++) {
                int col = nw * 32 + ni * 8 + g;
                bf[ni][0] = __float_as_uint(Bb[(k0 + t)     * BS_STR + col]);
                bf[ni][1] = __float_as_uint(Bb[(k0 + t + 4) * BS_STR + col]);
            }
            #pragma unroll
            for (int mi = 0; mi < 4; mi++)
                #pragma unroll
                for (int ni = 0; ni < 4; ni++)
                    mma8(acc[mi][ni], af[mi], bf[ni]);
        }
        __syncthreads();
    }

    // epilogue
    #pragma unroll
    for (int mi = 0; mi < 4; mi++) {
        #pragma unroll
        for (int ni = 0; ni < 4; ni++) {
            int r0  = m0 + mw * 64 + mi * 16 + g;
            int col = n0 + nw * 32 + ni * 8 + 2 * t;
            #pragma unroll
            for (int hh = 0; hh < 2; hh++) {
                int r = r0 + 8 * hh;
                #pragma unroll
                for (int q = 0; q < 2; q++) {
                    float v = acc[mi][ni][2 * hh + q];
                    int c = col + q;
                    if (bias) v += bias[c];
                    if (res)  v += res[(size_t)r * N + c];
                    if (GELU) v = 0.5f * v * (1.0f + erff(v * 0.70710678118654752f));
                    if (ROUND) v = rndf(v);
                    out[(size_t)r * N + c] = v;
                }
            }
        }
    }
}

// ============ attention scores: S = (Q Kt) * scale via mma ================
// per (b,h): Q[512,64] @ K^T[64,512]. CTA tile 128x128, full K=64 resident.
// Q,K pre-rounded to tf32 by QKV epilogue.
#define QS_STR 68
#define SC_SMEM (2*128*QS_STR*4)                   // 69632 B

__global__ void __launch_bounds__(256)
attn_scores_k() {
    extern __shared__ char dsm[];
    float* Qs = (float*)dsm;                       // [128][QS_STR]
    float* Ks = Qs + 128 * QS_STR;                 // [128][QS_STR]

    int tid = threadIdx.x;
    int wid = tid >> 5, lane = tid & 31;
    int g = lane >> 2, t = lane & 3;
    int mw = wid >> 2, nw = wid & 3;
    int z = blockIdx.z;                            // b*H + h
    int b = z >> 3, h = z & 7;
    int qt = blockIdx.y * 128, kt = blockIdx.x * 128;

    const float* qb = g_qkv + ((size_t)b * TT) * C3 + h * DH;
    const float* kb = g_qkv + ((size_t)b * TT) * C3 + CC + h * DH;
    #pragma unroll
    for (int i = 0; i < 8; i++) {
        int c = tid + i * 256;                     // 128 rows x 16 segs
        int r = c >> 4, s = c & 15;
        cp_async16(smem_u32(Qs + r * QS_STR + s * 4),
                   qb + (size_t)(qt + r) * C3 + s * 4);
        cp_async16(smem_u32(Ks + r * QS_STR + s * 4),
                   kb + (size_t)(kt + r) * C3 + s * 4);
    }
    cp_commit(); cp_wait<0>();
    __syncthreads();

    float acc[4][4][4] = {};
    #pragma unroll
    for (int ks = 0; ks < 8; ks++) {
        int k0 = ks * 8;
        uint32_t af[4][4], bf[4][2];
        #pragma unroll
        for (int mi = 0; mi < 4; mi++) {
            int row = mw * 64 + mi * 16;
            af[mi][0] = __float_as_uint(Qs[(row + g)     * QS_STR + k0 + t]);
            af[mi][1] = __float_as_uint(Qs[(row + 8 + g) * QS_STR + k0 + t]);
            af[mi][2] = __float_as_uint(Qs[(row + g)     * QS_STR + k0 + t + 4]);
            af[mi][3] = __float_as_uint(Qs[(row + 8 + g) * QS_STR + k0 + t + 4]);
        }
        #pragma unroll
        for (int ni = 0; ni < 4; ni++) {
            int col = nw * 32 + ni * 8 + g;        // K row = score column
            bf[ni][0] = __float_as_uint(Ks[col * QS_STR + k0 + t]);
            bf[ni][1] = __float_as_uint(Ks[col * QS_STR + k0 + t + 4]);
        }
        #pragma unroll
        for (int mi = 0; mi < 4; mi++)
            #pragma unroll
            for (int ni = 0; ni < 4; ni++)
                mma8(acc[mi][ni], af[mi], bf[ni]);
    }

    float* op = g_att + (size_t)z * TT * TT;
    #pragma unroll
    for (int mi = 0; mi < 4; mi++)
        #pragma unroll
        for (int ni = 0; ni < 4; ni++) {
            int r0  = qt + mw * 64 + mi * 16 + g;
            int col = kt + nw * 32 + ni * 8 + 2 * t;
            op[(size_t)r0       * TT + col]     = acc[mi][ni][0] * ATT_SCALE;
            op[(size_t)r0       * TT + col + 1] = acc[mi][ni][1] * ATT_SCALE;
            op[(size_t)(r0 + 8) * TT + col]     = acc[mi][ni][2] * ATT_SCALE;
            op[(size_t)(r0 + 8) * TT + col + 1] = acc[mi][ni][3] * ATT_SCALE;
        }
}

// ---------------- softmax (writes tf32-rounded probabilities) --------------
__device__ __forceinline__ float block_reduce_sum(float v, float* sm) {
    #pragma unroll
    for (int o = 16; o; o >>= 1) v += __shfl_xor_sync(0xffffffffu, v, o);
    int w = threadIdx.x >> 5;
    if ((threadIdx.x & 31) == 0) sm[w] = v;
    __syncthreads();
    if (threadIdx.x < 32) {
        float x = (threadIdx.x < 8) ? sm[threadIdx.x] : 0.0f;
        #pragma unroll
        for (int o = 4; o; o >>= 1) x += __shfl_xor_sync(0xffffffffu, x, o);
        if (threadIdx.x == 0) sm[0] = x;
    }
    __syncthreads();
    float r = sm[0];
    __syncthreads();
    return r;
}
__device__ __forceinline__ float block_reduce_max(float v, float* sm) {
    #pragma unroll
    for (int o = 16; o; o >>= 1) v = fmaxf(v, __shfl_xor_sync(0xffffffffu, v, o));
    int w = threadIdx.x >> 5;
    if ((threadIdx.x & 31) == 0) sm[w] = v;
    __syncthreads();
    if (threadIdx.x < 32) {
        float x = (threadIdx.x < 8) ? sm[threadIdx.x] : -1e30f;
        #pragma unroll
        for (int o = 4; o; o >>= 1) x = fmaxf(x, __shfl_xor_sync(0xffffffffu, x, o));
        if (threadIdx.x == 0) sm[0] = x;
    }
    __syncthreads();
    float r = sm[0];
    __syncthreads();
    return r;
}

__global__ void softmax_k() {
    __shared__ float sm[8];
    size_t row = blockIdx.x;
    float* p = g_att + row * TT;
    int t = threadIdx.x;
    float v0 = p[t], v1 = p[t + 256];
    float mx = block_reduce_max(fmaxf(v0, v1), sm);
    float e0 = expf(v0 - mx), e1 = expf(v1 - mx);
    float s = block_reduce_sum(e0 + e1, sm);
    float inv = 1.0f / s;
    p[t]       = rndf(e0 * inv);
    p[t + 256] = rndf(e1 * inv);
}

// ============ Y = P @ V via mma: per (b,h) [512,512]@[512,64] ==============
// P pre-rounded by softmax, V pre-rounded by QKV epilogue. Output rounded.
#define PS_STR 68
#define VS_STR 72
#define PV_SMEM (128*PS_STR*4 + 64*VS_STR*4)       // 53248 B

__global__ void __launch_bounds__(256)
attn_pv_k() {
    extern __shared__ char dsm[];
    float* Ps = (float*)dsm;                       // [128][PS_STR]
    float* Vs = Ps + 128 * PS_STR;                 // [64][VS_STR]

    int tid = threadIdx.x;
    int wid = tid >> 5, lane = tid & 31;
    int g = lane >> 2, t = lane & 3;
    int mw = wid & 3, nw = wid >> 2;               // warp grid 4(m) x 2(n), tile 32x32
    int z = blockIdx.y;
    int b = z >> 3, h = z & 7;
    int qt = blockIdx.x * 128;

    const float* pb = g_att + (size_t)z * TT * TT;
    const float* vb = g_qkv + ((size_t)b * TT) * C3 + 2 * CC + h * DH;

    float acc[2][4][4] = {};

    for (int kc = 0; kc < 8; kc++) {               // K chunks of 64
        int kk0 = kc * 64;
        __syncthreads();
        #pragma unroll
        for (int i = 0; i < 8; i++) {              // P: 128 rows x 16 segs
            int c = tid + i * 256;
            int r = c >> 4, s = c & 15;
            cp_async16(smem_u32(Ps + r * PS_STR + s * 4),
                       pb + (size_t)(qt + r) * TT + kk0 + s * 4);
        }
        #pragma unroll
        for (int i = 0; i < 4; i++) {              // V: 64 rows x 16 segs
            int c = tid + i * 256;
            int r = c >> 4, s = c & 15;
            cp_async16(smem_u32(Vs + r * VS_STR + s * 4),
                       vb + (size_t)(kk0 + r) * C3 + s * 4);
        }
        cp_commit(); cp_wait<0>();
        __syncthreads();

        #pragma unroll
        for (int ks = 0; ks < 8; ks++) {
            int k0 = ks * 8;
            uint32_t af[2][4], bf[4][2];
            #pragma unroll
            for (int mi = 0; mi < 2; mi++) {
                int row = mw * 32 + mi * 16;
                af[mi][0] = __float_as_uint(Ps[(row + g)     * PS_STR + k0 + t]);
                af[mi][1] = __float_as_uint(Ps[(row + 8 + g) * PS_STR + k0 + t]);
                af[mi][2] = __float_as_uint(Ps[(row + g)     * PS_STR + k0 + t + 4]);
                af[mi][3] = __float_as_uint(Ps[(row + 8 + g) * PS_STR + k0 + t + 4]);
            }
            #pragma unroll
            for (int ni = 0; ni < 4; ni++) {
                int col = nw * 32 + ni * 8 + g;
                bf[ni][0] = __float_as_uint(Vs[(k0 + t)     * VS_STR + col]);
                bf[ni][1] = __float_as_uint(Vs[(k0 + t + 4) * VS_STR + col]);
            }
            #pragma unroll
            for (int mi = 0; mi < 2; mi++)
                #pragma unroll
                for (int ni = 0; ni < 4; ni++)
                    mma8(acc[mi][ni], af[mi], bf[ni]);
        }
    }

    float* yb = g_y + ((size_t)b * TT) * CC + h * DH;
    #pragma unroll
    for (int mi = 0; mi < 2; mi++)
        #pragma unroll
        for (int ni = 0; ni < 4; ni++) {
            int r0  = qt + mw * 32 + mi * 16 + g;
            int col = nw * 32 + ni * 8 + 2 * t;
            yb[(size_t)r0       * CC + col]     = rndf(acc[mi][ni][0]);
            yb[(size_t)r0       * CC + col + 1] = rndf(acc[mi][ni][1]);
            yb[(size_t)(r0 + 8) * CC + col]     = rndf(acc[mi][ni][2]);
            yb[(size_t)(r0 + 8) * CC + col + 1] = rndf(acc[mi][ni][3]);
        }
}

// ---------------- embedding ----------------
__global__ void embed_k(const int* __restrict__ idx, const float* __restrict__ tok,
                        const float* __restrict__ pos) {
    int i = blockIdx.x * blockDim.x + threadIdx.x;
    int m = i / CC, c = i - m * CC;
    int t = m & (TT - 1);
    g_x[i] = tok[idx[m] * CC + c] + pos[t * CC + c];
}

// ---------------- layernorm (output rounded to tf32) ----------------
__global__ void ln_k(const float* __restrict__ in, const float* __restrict__ gam,
                     const float* __restrict__ bet, float* __restrict__ out) {
    __shared__ float sm[8];
    int row = blockIdx.x;
    const float* x = in + (size_t)row * CC;
    int t = threadIdx.x;
    float v0 = x[t], v1 = x[t + 256];
    float mean = block_reduce_sum(v0 + v1, sm) * (1.0f / CC);
    float d0 = v0 - mean, d1 = v1 - mean;
    float var = block_reduce_sum(d0 * d0 + d1 * d1, sm) * (1.0f / CC);
    float rstd = rsqrtf(var + 1e-5f);
    float* o = out + (size_t)row * CC;
    o[t]       = rndf(d0 * rstd * gam[t]       + bet[t]);
    o[t + 256] = rndf(d1 * rstd * gam[t + 256] + bet[t + 256]);
}

// ---------------- host orchestration ----------------
extern "C" void kernel_launch(void* const* d_in, const int* in_sizes, int n_in,
                              void* d_out, int out_size) {
    const int*   idx  = (const int*)  d_in[0];
    const float* tok  = (const float*)d_in[1];
    const float* pos  = (const float*)d_in[2];
    const float* ln1g = (const float*)d_in[3];
    const float* ln1b = (const float*)d_in[4];
    const float* Wq   = (const float*)d_in[5];
    const float* bq   = (const float*)d_in[6];
    const float* Wk   = (const float*)d_in[7];
    const float* bk   = (const float*)d_in[8];
    const float* Wv   = (const float*)d_in[9];
    const float* bv   = (const float*)d_in[10];
    const float* Wp   = (const float*)d_in[11];
    const float* bp   = (const float*)d_in[12];
    const float* ln2g = (const float*)d_in[13];
    const float* ln2b = (const float*)d_in[14];
    const float* W1   = (const float*)d_in[15];
    const float* b1   = (const float*)d_in[16];
    const float* W2   = (const float*)d_in[17];
    const float* b2   = (const float*)d_in[18];
    const float* lnfg = (const float*)d_in[19];
    const float* lnfb = (const float*)d_in[20];
    const float* Wh   = (const float*)d_in[21];
    float* out = (float*)d_out;

    float *px, *pxn, *pqkv, *py, *ph;
    float *pwqkv, *pbqkv, *pwp, *pw1, *pw2, *pwh;
    cudaGetSymbolAddress((void**)&px,    g_x);
    cudaGetSymbolAddress((void**)&pxn,   g_xn);
    cudaGetSymbolAddress((void**)&pqkv,  g_qkv);
    cudaGetSymbolAddress((void**)&py,    g_y);
    cudaGetSymbolAddress((void**)&ph,    g_h);
    cudaGetSymbolAddress((void**)&pwqkv, g_wqkv);
    cudaGetSymbolAddress((void**)&pbqkv, g_bqkv);
    cudaGetSymbolAddress((void**)&pwp,   g_wp);
    cudaGetSymbolAddress((void**)&pw1,   g_w1);
    cudaGetSymbolAddress((void**)&pw2,   g_w2);
    cudaGetSymbolAddress((void**)&pwh,   g_wh);

    cudaFuncSetAttribute(mma_gemm_k<false,false>,
                         cudaFuncAttributeMaxDynamicSharedMemorySize, GEMM_SMEM);
    cudaFuncSetAttribute(mma_gemm_k<false,true>,
                         cudaFuncAttributeMaxDynamicSharedMemorySize, GEMM_SMEM);
    cudaFuncSetAttribute(mma_gemm_k<true,true>,
                         cudaFuncAttributeMaxDynamicSharedMemorySize, GEMM_SMEM);
    cudaFuncSetAttribute(attn_scores_k,
                         cudaFuncAttributeMaxDynamicSharedMemorySize, SC_SMEM);
    cudaFuncSetAttribute(attn_pv_k,
                         cudaFuncAttributeMaxDynamicSharedMemorySize, PV_SMEM);

    // weight preprocessing (tf32 pre-rounding + QKV concat)
    prep_wqkv_k<<<(2 * CC * CC + 255) / 256, 256>>>(Wq, Wk, Wv);
    prep_bqkv_k<<<(2 * CC + 255) / 256, 256>>>(bq, bk, bv);
    prep_round_k<<<(2 * CC * CC + 255) / 256, 256>>>(Wp, pwp, 2 * CC * CC);
    prep_round_k<<<(2 * CC * CF + 255) / 256, 256>>>(W1, pw1, 2 * CC * CF);
    prep_round_k<<<(2 * CF * CC + 255) / 256, 256>>>(W2, pw2, 2 * CF * CC);
    prep_round_k<<<(CC * VV + 255) / 256, 256>>>(Wh, pwh, CC * VV);

    embed_k<<<(MTOK * CC) / 256, 256>>>(idx, tok, pos);

    dim3 gQKV(C3 / 128, MTOK / 128);    // (12, 32)
    dim3 gCC(CC / 128, MTOK / 128);     // (4, 32)
    dim3 gCF(CF / 128, MTOK / 128);     // (16, 32)
    dim3 gS(4, 4, BB * HH);             // scores: 128x128 tiles
    dim3 gPV(4, BB * HH);               // pv: 128-row tiles

    for (int step = 0; step < NSTEPS; step++) {
        for (int l = 0; l < 2; l++) {
            size_t bo  = (size_t)l * CC;
            size_t b1o = (size_t)l * CF;

            ln_k<<<MTOK, 256>>>(px, ln1g + bo, ln1b + bo, pxn);
            mma_gemm_k<false,true><<<gQKV, 256, GEMM_SMEM>>>(
                pxn, pwqkv + (size_t)l * CC * C3, pbqkv + (size_t)l * C3,
                nullptr, pqkv, MTOK, C3, CC);
            attn_scores_k<<<gS, 256, SC_SMEM>>>();
            softmax_k<<<BB * HH * TT, 256>>>();
            attn_pv_k<<<gPV, 256, PV_SMEM>>>();
            // x = x + y @ Wp + bp
            mma_gemm_k<false,false><<<gCC, 256, GEMM_SMEM>>>(
                py, pwp + (size_t)l * CC * CC, bp + bo, px, px, MTOK, CC, CC);

            ln_k<<<MTOK, 256>>>(px, ln2g + bo, ln2b + bo, pxn);
            mma_gemm_k<true,true><<<gCF, 256, GEMM_SMEM>>>(
                pxn, pw1 + (size_t)l * CC * CF, b1 + b1o, nullptr, ph, MTOK, CF, CC);
            // x = x + h @ W2 + b2
            mma_gemm_k<false,false><<<gCC, 256, GEMM_SMEM>>>(
                ph, pw2 + (size_t)l * CF * CC, b2 + bo, px, px, MTOK, CC, CF);
        }
    }

    ln_k<<<MTOK, 256>>>(px, lnfg, lnfb, pxn);
    mma_gemm_k<false,false><<<dim3(VV / 128, MTOK / 128), 256, GEMM_SMEM>>>(
        pxn, pwh, nullptr, nullptr, out, MTOK, VV, CC);
}

// round 7
// speedup vs baseline: 1.4660x; 1.4660x over previous
#include <cuda_runtime.h>
#include <cstdint>
#include <math.h>

#define BB 8
#define TT 512
#define CC 512
#define HH 8
#define DH 64
#define CF 2048
#define MTOK (BB*TT)      // 4096
#define VV 512
#define NSTEPS 4
#define ATT_SCALE 0.125f  // 1/sqrt(64)

// ---------------- scratch (device globals: no allocations allowed) ----------
__device__ float g_x [MTOK*CC];
__device__ float g_xn[MTOK*CC];
__device__ float g_q [MTOK*CC];
__device__ float g_k [MTOK*CC];
__device__ float g_v [MTOK*CC];
__device__ float g_y [MTOK*CC];
__device__ float g_h [MTOK*CF];
__device__ float g_att[(size_t)BB*HH*TT*TT];
// pre-rounded (tf32) weights
__device__ float g_wq[2*CC*CC];
__device__ float g_wk[2*CC*CC];
__device__ float g_wv[2*CC*CC];
__device__ float g_wp[2*CC*CC];
__device__ float g_w1[2*CC*CF];
__device__ float g_w2[2*CF*CC];
__device__ float g_wh[CC*VV];

// ======================= helpers ==============================
__device__ __forceinline__ uint32_t smem_u32(const void* p) {
    uint32_t a;
    asm("{ .reg .u64 t; cvta.to.shared.u64 t, %1; cvt.u32.u64 %0, t; }"
        : "=r"(a) : "l"(p));
    return a;
}
__device__ __forceinline__ void cp_async16(uint32_t dst, const void* src) {
    asm volatile("cp.async.cg.shared.global [%0], [%1], 16;" :: "r"(dst), "l"(src));
}
__device__ __forceinline__ void cp_commit() {
    asm volatile("cp.async.commit_group;" ::: "memory");
}
template <int N>
__device__ __forceinline__ void cp_wait() {
    asm volatile("cp.async.wait_group %0;" :: "n"(N) : "memory");
}
__device__ __forceinline__ uint32_t f2tf32(float x) {
    uint32_t r;
    asm("cvt.rna.tf32.f32 %0, %1;" : "=r"(r) : "f"(x));
    return r;
}
__device__ __forceinline__ float rndf(float x) { return __uint_as_float(f2tf32(x)); }
// D += A @ B  (m16n8k8, tf32 in, fp32 accumulate)
__device__ __forceinline__ void mma8(float* c, const uint32_t* a, const uint32_t* b) {
    asm volatile(
        "mma.sync.aligned.m16n8k8.row.col.f32.tf32.tf32.f32 "
        "{%0,%1,%2,%3}, {%4,%5,%6,%7}, {%8,%9}, {%0,%1,%2,%3};"
        : "+f"(c[0]), "+f"(c[1]), "+f"(c[2]), "+f"(c[3])
        : "r"(a[0]), "r"(a[1]), "r"(a[2]), "r"(a[3]), "r"(b[0]), "r"(b[1]));
}

// ---------------- weight pre-rounding (tf32) ----------------
__global__ void prep3_k(const float* __restrict__ a, const float* __restrict__ b,
                        const float* __restrict__ c, float* __restrict__ da,
                        float* __restrict__ db, float* __restrict__ dc, int n) {
    int i = blockIdx.x * 256 + threadIdx.x;
    if (i < n) { da[i] = rndf(a[i]); db[i] = rndf(b[i]); dc[i] = rndf(c[i]); }
}
__global__ void prep1_k(const float* __restrict__ src, float* __restrict__ dst, int n) {
    int i = blockIdx.x * 256 + threadIdx.x;
    if (i < n) dst[i] = rndf(src[i]);
}

// ================== dense GEMM: out = epi(A@W + bias + res) ================
// A, W pre-rounded tf32. CTA 128x128, 8 warps (2x4), warp tile 64x32,
// K-chunk 32, cp.async double buffered. NO cvt in mainloop.
#define AS_STR 36
#define BS_STR 136
#define GEMM_SMEM (2*128*AS_STR*4 + 2*32*BS_STR*4)   // 71680 B

template <bool GELU, bool ROUND>
__global__ void __launch_bounds__(256)
mma_gemm_k(const float* __restrict__ A, const float* __restrict__ W,
           const float* __restrict__ bias, const float* __restrict__ res,
           float* __restrict__ out, int M, int N, int K) {
    extern __shared__ char dsm[];
    float* As = (float*)dsm;                       // [2][128][AS_STR]
    float* Bs = As + 2 * 128 * AS_STR;             // [2][32][BS_STR]

    int tid = threadIdx.x;
    int wid = tid >> 5, lane = tid & 31;
    int g = lane >> 2, t = lane & 3;
    int mw = wid >> 2, nw = wid & 3;               // warp grid 2x4
    int m0 = blockIdx.y * 128, n0 = blockIdx.x * 128;

    auto loadA = [&](int chunk, int buf) {
        const float* src = A + (size_t)m0 * K + chunk * 32;
        float* dst = As + buf * 128 * AS_STR;
        #pragma unroll
        for (int i = 0; i < 4; i++) {
            int c = tid + i * 256;
            int m = c >> 3, s = c & 7;
            cp_async16(smem_u32(dst + m * AS_STR + s * 4),
                       src + (size_t)m * K + s * 4);
        }
    };
    auto loadB = [&](int chunk, int buf) {
        const float* src = W + (size_t)(chunk * 32) * N + n0;
        float* dst = Bs + buf * 32 * BS_STR;
        #pragma unroll
        for (int i = 0; i < 4; i++) {
            int c = tid + i * 256;
            int k = c >> 5, s = c & 31;
            cp_async16(smem_u32(dst + k * BS_STR + s * 4),
                       src + (size_t)k * N + s * 4);
        }
    };

    float acc[4][4][4];
    #pragma unroll
    for (int mi = 0; mi < 4; mi++)
        #pragma unroll
        for (int ni = 0; ni < 4; ni++)
            #pragma unroll
            for (int q = 0; q < 4; q++) acc[mi][ni][q] = 0.0f;

    const int nch = K >> 5;
    loadA(0, 0); loadB(0, 0); cp_commit();

    for (int i = 0; i < nch; i++) {
        int buf = i & 1;
        if (i + 1 < nch) {
            loadA(i + 1, buf ^ 1); loadB(i + 1, buf ^ 1); cp_commit();
            cp_wait<1>();
        } else {
            cp_wait<0>();
        }
        __syncthreads();
        const float* Ab = As + buf * 128 * AS_STR;
        const float* Bb = Bs + buf * 32 * BS_STR;
        #pragma unroll
        for (int ks = 0; ks < 4; ks++) {
            int k0 = ks * 8;
            uint32_t af[4][4], bf[4][2];
            #pragma unroll
            for (int mi = 0; mi < 4; mi++) {
                int row = mw * 64 + mi * 16;
                af[mi][0] = __float_as_uint(Ab[(row + g)     * AS_STR + k0 + t]);
                af[mi][1] = __float_as_uint(Ab[(row + 8 + g) * AS_STR + k0 + t]);
                af[mi][2] = __float_as_uint(Ab[(row + g)     * AS_STR + k0 + t + 4]);
                af[mi][3] = __float_as_uint(Ab[(row + 8 + g) * AS_STR + k0 + t + 4]);
            }
            #pragma unroll
            for (int ni = 0; ni < 4; ni++) {
                int col = nw * 32 + ni * 8 + g;
                bf[ni][0] = __float_as_uint(Bb[(k0 + t)     * BS_STR + col]);
                bf[ni][1] = __float_as_uint(Bb[(k0 + t + 4) * BS_STR + col]);
            }
            #pragma unroll
            for (int mi = 0; mi < 4; mi++)
                #pragma unroll
                for (int ni = 0; ni < 4; ni++)
                    mma8(acc[mi][ni], af[mi], bf[ni]);
        }
        __syncthreads();
    }

    // epilogue
    #pragma unroll
    for (int mi = 0; mi < 4; mi++) {
        #pragma unroll
        for (int ni = 0; ni < 4; ni++) {
            int r0  = m0 + mw * 64 + mi * 16 + g;
            int col = n0 + nw * 32 + ni * 8 + 2 * t;
            #pragma unroll
            for (int hh = 0; hh < 2; hh++) {
                int r = r0 + 8 * hh;
                #pragma unroll
                for (int q = 0; q < 2; q++) {
                    float v = acc[mi][ni][2 * hh + q];
                    int c = col + q;
                    if (bias) v += bias[c];
                    if (res)  v += res[(size_t)r * N + c];
                    if (GELU) v = 0.5f * v * (1.0f + erff(v * 0.70710678118654752f));
                    if (ROUND) v = rndf(v);
                    out[(size_t)r * N + c] = v;
                }
            }
        }
    }
}

// ============ attention scores: S = (Q Kt) * scale via mma ================
// Q,K pre-rounded by QKV GEMM epilogues. CTA tile 128x128, full K=64 resident.
#define QS_STR 68
#define SC_SMEM (2*128*QS_STR*4)                   // 69632 B

__global__ void __launch_bounds__(256)
attn_scores_k() {
    extern __shared__ char dsm[];
    float* Qs = (float*)dsm;                       // [128][QS_STR]
    float* Ks = Qs + 128 * QS_STR;                 // [128][QS_STR]

    int tid = threadIdx.x;
    int wid = tid >> 5, lane = tid & 31;
    int g = lane >> 2, t = lane & 3;
    int mw = wid >> 2, nw = wid & 3;
    int z = blockIdx.z;                            // b*H + h
    int b = z >> 3, h = z & 7;
    int qt = blockIdx.y * 128, kt = blockIdx.x * 128;

    const float* qb = g_q + ((size_t)b * TT) * CC + h * DH;
    const float* kb = g_k + ((size_t)b * TT) * CC + h * DH;
    #pragma unroll
    for (int i = 0; i < 8; i++) {
        int c = tid + i * 256;                     // 128 rows x 16 segs
        int r = c >> 4, s = c & 15;
        cp_async16(smem_u32(Qs + r * QS_STR + s * 4),
                   qb + (size_t)(qt + r) * CC + s * 4);
        cp_async16(smem_u32(Ks + r * QS_STR + s * 4),
                   kb + (size_t)(kt + r) * CC + s * 4);
    }
    cp_commit(); cp_wait<0>();
    __syncthreads();

    float acc[4][4][4] = {};
    #pragma unroll
    for (int ks = 0; ks < 8; ks++) {
        int k0 = ks * 8;
        uint32_t af[4][4], bf[4][2];
        #pragma unroll
        for (int mi = 0; mi < 4; mi++) {
            int row = mw * 64 + mi * 16;
            af[mi][0] = __float_as_uint(Qs[(row + g)     * QS_STR + k0 + t]);
            af[mi][1] = __float_as_uint(Qs[(row + 8 + g) * QS_STR + k0 + t]);
            af[mi][2] = __float_as_uint(Qs[(row + g)     * QS_STR + k0 + t + 4]);
            af[mi][3] = __float_as_uint(Qs[(row + 8 + g) * QS_STR + k0 + t + 4]);
        }
        #pragma unroll
        for (int ni = 0; ni < 4; ni++) {
            int col = nw * 32 + ni * 8 + g;        // K row = score column
            bf[ni][0] = __float_as_uint(Ks[col * QS_STR + k0 + t]);
            bf[ni][1] = __float_as_uint(Ks[col * QS_STR + k0 + t + 4]);
        }
        #pragma unroll
        for (int mi = 0; mi < 4; mi++)
            #pragma unroll
            for (int ni = 0; ni < 4; ni++)
                mma8(acc[mi][ni], af[mi], bf[ni]);
    }

    float* op = g_att + (size_t)z * TT * TT;
    #pragma unroll
    for (int mi = 0; mi < 4; mi++)
        #pragma unroll
        for (int ni = 0; ni < 4; ni++) {
            int r0  = qt + mw * 64 + mi * 16 + g;
            int col = kt + nw * 32 + ni * 8 + 2 * t;
            op[(size_t)r0       * TT + col]     = acc[mi][ni][0] * ATT_SCALE;
            op[(size_t)r0       * TT + col + 1] = acc[mi][ni][1] * ATT_SCALE;
            op[(size_t)(r0 + 8) * TT + col]     = acc[mi][ni][2] * ATT_SCALE;
            op[(size_t)(r0 + 8) * TT + col + 1] = acc[mi][ni][3] * ATT_SCALE;
        }
}

// ---------------- block reductions ----------------
__device__ __forceinline__ float block_reduce_sum(float v, float* sm) {
    #pragma unroll
    for (int o = 16; o; o >>= 1) v += __shfl_xor_sync(0xffffffffu, v, o);
    int w = threadIdx.x >> 5;
    if ((threadIdx.x & 31) == 0) sm[w] = v;
    __syncthreads();
    if (threadIdx.x < 32) {
        float x = (threadIdx.x < 8) ? sm[threadIdx.x] : 0.0f;
        #pragma unroll
        for (int o = 4; o; o >>= 1) x += __shfl_xor_sync(0xffffffffu, x, o);
        if (threadIdx.x == 0) sm[0] = x;
    }
    __syncthreads();
    float r = sm[0];
    __syncthreads();
    return r;
}
__device__ __forceinline__ float block_reduce_max(float v, float* sm) {
    #pragma unroll
    for (int o = 16; o; o >>= 1) v = fmaxf(v, __shfl_xor_sync(0xffffffffu, v, o));
    int w = threadIdx.x >> 5;
    if ((threadIdx.x & 31) == 0) sm[w] = v;
    __syncthreads();
    if (threadIdx.x < 32) {
        float x = (threadIdx.x < 8) ? sm[threadIdx.x] : -1e30f;
        #pragma unroll
        for (int o = 4; o; o >>= 1) x = fmaxf(x, __shfl_xor_sync(0xffffffffu, x, o));
        if (threadIdx.x == 0) sm[0] = x;
    }
    __syncthreads();
    float r = sm[0];
    __syncthreads();
    return r;
}

// ---------------- softmax (writes tf32-rounded probabilities) --------------
__global__ void softmax_k() {
    __shared__ float sm[8];
    size_t row = blockIdx.x;
    float* p = g_att + row * TT;
    int t = threadIdx.x;
    float v0 = p[t], v1 = p[t + 256];
    float mx = block_reduce_max(fmaxf(v0, v1), sm);
    float e0 = expf(v0 - mx), e1 = expf(v1 - mx);
    float s = block_reduce_sum(e0 + e1, sm);
    float inv = 1.0f / s;
    p[t]       = rndf(e0 * inv);
    p[t + 256] = rndf(e1 * inv);
}

// ============ Y = P @ V via mma: per (b,h) [512,512]@[512,64] ==============
// P, V pre-rounded; output y rounded (feeds proj GEMM cvt-free).
#define PS_STR 68
#define VS_STR 72
#define PV_SMEM (128*PS_STR*4 + 64*VS_STR*4)       // 53248 B

__global__ void __launch_bounds__(256)
attn_pv_k() {
    extern __shared__ char dsm[];
    float* Ps = (float*)dsm;                       // [128][PS_STR]
    float* Vs = Ps + 128 * PS_STR;                 // [64][VS_STR]

    int tid = threadIdx.x;
    int wid = tid >> 5, lane = tid & 31;
    int g = lane >> 2, t = lane & 3;
    int mw = wid & 3, nw = wid >> 2;               // warp grid 4(m) x 2(n)
    int z = blockIdx.y;
    int b = z >> 3, h = z & 7;
    int qt = blockIdx.x * 128;

    const float* pb = g_att + (size_t)z * TT * TT;
    const float* vb = g_v + ((size_t)b * TT) * CC + h * DH;

    float acc[2][4][4] = {};

    for (int kc = 0; kc < 8; kc++) {               // K chunks of 64
        int kk0 = kc * 64;
        __syncthreads();
        #pragma unroll
        for (int i = 0; i < 8; i++) {              // P: 128 rows x 16 segs
            int c = tid + i * 256;
            int r = c >> 4, s = c & 15;
            cp_async16(smem_u32(Ps + r * PS_STR + s * 4),
                       pb + (size_t)(qt + r) * TT + kk0 + s * 4);
        }
        #pragma unroll
        for (int i = 0; i < 4; i++) {              // V: 64 rows x 16 segs
            int c = tid + i * 256;
            int r = c >> 4, s = c & 15;
            cp_async16(smem_u32(Vs + r * VS_STR + s * 4),
                       vb + (size_t)(kk0 + r) * CC + s * 4);
        }
        cp_commit(); cp_wait<0>();
        __syncthreads();

        #pragma unroll
        for (int ks = 0; ks < 8; ks++) {
            int k0 = ks * 8;
            uint32_t af[2][4], bf[4][2];
            #pragma unroll
            for (int mi = 0; mi < 2; mi++) {
                int row = mw * 32 + mi * 16;
                af[mi][0] = __float_as_uint(Ps[(row + g)     * PS_STR + k0 + t]);
                af[mi][1] = __float_as_uint(Ps[(row + 8 + g) * PS_STR + k0 + t]);
                af[mi][2] = __float_as_uint(Ps[(row + g)     * PS_STR + k0 + t + 4]);
                af[mi][3] = __float_as_uint(Ps[(row + 8 + g) * PS_STR + k0 + t + 4]);
            }
            #pragma unroll
            for (int ni = 0; ni < 4; ni++) {
                int col = nw * 32 + ni * 8 + g;
                bf[ni][0] = __float_as_uint(Vs[(k0 + t)     * VS_STR + col]);
                bf[ni][1] = __float_as_uint(Vs[(k0 + t + 4) * VS_STR + col]);
            }
            #pragma unroll
            for (int mi = 0; mi < 2; mi++)
                #pragma unroll
                for (int ni = 0; ni < 4; ni++)
                    mma8(acc[mi][ni], af[mi], bf[ni]);
        }
    }

    float* yb = g_y + ((size_t)b * TT) * CC + h * DH;
    #pragma unroll
    for (int mi = 0; mi < 2; mi++)
        #pragma unroll
        for (int ni = 0; ni < 4; ni++) {
            int r0  = qt + mw * 32 + mi * 16 + g;
            int col = nw * 32 + ni * 8 + 2 * t;
            yb[(size_t)r0       * CC + col]     = rndf(acc[mi][ni][0]);
            yb[(size_t)r0       * CC + col + 1] = rndf(acc[mi][ni][1]);
            yb[(size_t)(r0 + 8) * CC + col]     = rndf(acc[mi][ni][2]);
            yb[(size_t)(r0 + 8) * CC + col + 1] = rndf(acc[mi][ni][3]);
        }
}

// ---------------- embedding ----------------
__global__ void embed_k(const int* __restrict__ idx, const float* __restrict__ tok,
                        const float* __restrict__ pos) {
    int i = blockIdx.x * blockDim.x + threadIdx.x;
    int m = i / CC, c = i - m * CC;
    int t = m & (TT - 1);
    g_x[i] = tok[idx[m] * CC + c] + pos[t * CC + c];
}

// ---------------- layernorm (output rounded to tf32) ----------------
__global__ void ln_k(const float* __restrict__ in, const float* __restrict__ gam,
                     const float* __restrict__ bet, float* __restrict__ out) {
    __shared__ float sm[8];
    int row = blockIdx.x;
    const float* x = in + (size_t)row * CC;
    int t = threadIdx.x;
    float v0 = x[t], v1 = x[t + 256];
    float mean = block_reduce_sum(v0 + v1, sm) * (1.0f / CC);
    float d0 = v0 - mean, d1 = v1 - mean;
    float var = block_reduce_sum(d0 * d0 + d1 * d1, sm) * (1.0f / CC);
    float rstd = rsqrtf(var + 1e-5f);
    float* o = out + (size_t)row * CC;
    o[t]       = rndf(d0 * rstd * gam[t]       + bet[t]);
    o[t + 256] = rndf(d1 * rstd * gam[t + 256] + bet[t + 256]);
}

// ---------------- host orchestration ----------------
extern "C" void kernel_launch(void* const* d_in, const int* in_sizes, int n_in,
                              void* d_out, int out_size) {
    const int*   idx  = (const int*)  d_in[0];
    const float* tok  = (const float*)d_in[1];
    const float* pos  = (const float*)d_in[2];
    const float* ln1g = (const float*)d_in[3];
    const float* ln1b = (const float*)d_in[4];
    const float* Wq   = (const float*)d_in[5];
    const float* bq   = (const float*)d_in[6];
    const float* Wk   = (const float*)d_in[7];
    const float* bk   = (const float*)d_in[8];
    const float* Wv   = (const float*)d_in[9];
    const float* bv   = (const float*)d_in[10];
    const float* Wp   = (const float*)d_in[11];
    const float* bp   = (const float*)d_in[12];
    const float* ln2g = (const float*)d_in[13];
    const float* ln2b = (const float*)d_in[14];
    const float* W1   = (const float*)d_in[15];
    const float* b1   = (const float*)d_in[16];
    const float* W2   = (const float*)d_in[17];
    const float* b2   = (const float*)d_in[18];
    const float* lnfg = (const float*)d_in[19];
    const float* lnfb = (const float*)d_in[20];
    const float* Wh   = (const float*)d_in[21];
    float* out = (float*)d_out;

    float *px, *pxn, *pq, *pk, *pv, *py, *ph;
    float *pwq, *pwk, *pwv, *pwp, *pw1, *pw2, *pwh;
    cudaGetSymbolAddress((void**)&px,  g_x);
    cudaGetSymbolAddress((void**)&pxn, g_xn);
    cudaGetSymbolAddress((void**)&pq,  g_q);
    cudaGetSymbolAddress((void**)&pk,  g_k);
    cudaGetSymbolAddress((void**)&pv,  g_v);
    cudaGetSymbolAddress((void**)&py,  g_y);
    cudaGetSymbolAddress((void**)&ph,  g_h);
    cudaGetSymbolAddress((void**)&pwq, g_wq);
    cudaGetSymbolAddress((void**)&pwk, g_wk);
    cudaGetSymbolAddress((void**)&pwv, g_wv);
    cudaGetSymbolAddress((void**)&pwp, g_wp);
    cudaGetSymbolAddress((void**)&pw1, g_w1);
    cudaGetSymbolAddress((void**)&pw2, g_w2);
    cudaGetSymbolAddress((void**)&pwh, g_wh);

    cudaFuncSetAttribute(mma_gemm_k<false,false>,
                         cudaFuncAttributeMaxDynamicSharedMemorySize, GEMM_SMEM);
    cudaFuncSetAttribute(mma_gemm_k<false,true>,
                         cudaFuncAttributeMaxDynamicSharedMemorySize, GEMM_SMEM);
    cudaFuncSetAttribute(mma_gemm_k<true,true>,
                         cudaFuncAttributeMaxDynamicSharedMemorySize, GEMM_SMEM);
    cudaFuncSetAttribute(attn_scores_k,
                         cudaFuncAttributeMaxDynamicSharedMemorySize, SC_SMEM);
    cudaFuncSetAttribute(attn_pv_k,
                         cudaFuncAttributeMaxDynamicSharedMemorySize, PV_SMEM);

    // weight pre-rounding (tf32) — 3 launches total
    prep3_k<<<(2 * CC * CC + 255) / 256, 256>>>(Wq, Wk, Wv, pwq, pwk, pwv, 2 * CC * CC);
    prep3_k<<<(2 * CC * CF + 255) / 256, 256>>>(W1, W2, W1, pw1, pw2, pw1, 2 * CC * CF);
    prep3_k<<<(CC * VV + 255) / 256, 256>>>(Wp, Wp + CC * CC, Wh, pwp, pwp + CC * CC, pwh, CC * VV);

    embed_k<<<(MTOK * CC) / 256, 256>>>(idx, tok, pos);

    dim3 gCC(CC / 128, MTOK / 128);     // (4, 32)
    dim3 gCF(CF / 128, MTOK / 128);     // (16, 32)
    dim3 gS(4, 4, BB * HH);             // scores: 128x128 tiles
    dim3 gPV(4, BB * HH);               // pv: 128-row tiles

    for (int step = 0; step < NSTEPS; step++) {
        for (int l = 0; l < 2; l++) {
            size_t wo  = (size_t)l * CC * CC;
            size_t bo  = (size_t)l * CC;
            size_t w1o = (size_t)l * CC * CF;
            size_t b1o = (size_t)l * CF;

            ln_k<<<MTOK, 256>>>(px, ln1g + bo, ln1b + bo, pxn);
            mma_gemm_k<false,true><<<gCC, 256, GEMM_SMEM>>>(pxn, pwq + wo, bq + bo, nullptr, pq, MTOK, CC, CC);
            mma_gemm_k<false,true><<<gCC, 256, GEMM_SMEM>>>(pxn, pwk + wo, bk + bo, nullptr, pk, MTOK, CC, CC);
            mma_gemm_k<false,true><<<gCC, 256, GEMM_SMEM>>>(pxn, pwv + wo, bv + bo, nullptr, pv, MTOK, CC, CC);
            attn_scores_k<<<gS, 256, SC_SMEM>>>();
            softmax_k<<<BB * HH * TT, 256>>>();
            attn_pv_k<<<gPV, 256, PV_SMEM>>>();
            // x = x + y @ Wp + bp
            mma_gemm_k<false,false><<<gCC, 256, GEMM_SMEM>>>(py, pwp + wo, bp + bo, px, px, MTOK, CC, CC);

            ln_k<<<MTOK, 256>>>(px, ln2g + bo, ln2b + bo, pxn);
            mma_gemm_k<true,true><<<gCF, 256, GEMM_SMEM>>>(pxn, pw1 + w1o, b1 + b1o, nullptr, ph, MTOK, CF, CC);
            // x = x + h @ W2 + b2
            mma_gemm_k<false,false><<<gCC, 256, GEMM_SMEM>>>(ph, pw2 + w1o, b2 + bo, px, px, MTOK, CC, CF);
        }
    }

    ln_k<<<MTOK, 256>>>(px, lnfg, lnfb, pxn);
    mma_gemm_k<false,false><<<dim3(VV / 128, MTOK / 128), 256, GEMM_SMEM>>>(
        pxn, pwh, nullptr, nullptr, out, MTOK, VV, CC);
}